// round 4
// baseline (speedup 1.0000x reference)
#include <cuda_runtime.h>
#include <cstdint>

#define CC   128
#define HH   56
#define NB   64
#define HW   3136
#define PW   58
#define PPI  (PW*PW)             // 3364
#define PTOT (NB*PPI)            // 215296
#define NTIL (PTOT/128)          // 1682
#define GUARD 64
#define NPX  (NB*HW)             // 200704

// ---------------- device scratch (zero-init at load; halo/guards never written) ----
__device__ unsigned g_alphaBits[2];
__device__ double   g_red[2][2][CC];
__device__ float    g_coef[2][2][CC];
__device__ __align__(128) signed char g_act8[(size_t)(PTOT + 2*GUARD) * CC]; // NHWC padded, k in 0..15
__device__ __align__(128) signed char g_wp8[2][9 * 128 * 128];               // [tap][oc][ci], m in -7..7
__device__ float    g_y[(size_t)PTOT * CC];                                   // S, NHWC f32 (exact ints)

__constant__ int c_off[9] = {-59,-58,-57,-1,0,1,57,58,59};

// ---------------- helpers ----------------
__device__ __forceinline__ uint32_t smem_u32(const void* p) {
    uint32_t a; asm("{ .reg .u64 t; cvta.to.shared.u64 t, %1; cvt.u32.u64 %0, t; }":"=r"(a):"l"(p));
    return a;
}
__device__ __forceinline__ void cp16(uint32_t dst, unsigned long long src) {
    asm volatile("cp.async.cg.shared.global [%0], [%1], 16;"::"r"(dst),"l"(src));
}
#define CP_COMMIT() asm volatile("cp.async.commit_group;":::"memory")
#define CP_WAIT(n)  asm volatile("cp.async.wait_group %0;"::"n"(n):"memory")

__device__ __forceinline__ void mma_s8(int* c, unsigned a0, unsigned a1, unsigned a2, unsigned a3,
                                       unsigned b0, unsigned b1) {
    asm volatile("mma.sync.aligned.m16n8k32.row.col.s32.s8.s8.s32 "
                 "{%0,%1,%2,%3}, {%4,%5,%6,%7}, {%8,%9}, {%0,%1,%2,%3};"
                 : "+r"(c[0]), "+r"(c[1]), "+r"(c[2]), "+r"(c[3])
                 : "r"(a0), "r"(a1), "r"(a2), "r"(a3), "r"(b0), "r"(b1));
}

// ---------------- small kernels ----------------
__global__ void k_zero() {
    int t = blockIdx.x*blockDim.x + threadIdx.x;
    if (t < 2) g_alphaBits[t] = 0u;
    if (t < 512) ((double*)g_red)[t] = 0.0;
}
__global__ void k_alpha(const float* __restrict__ w1, const float* __restrict__ w2) {
    const float* w = blockIdx.y ? w2 : w1;
    float m = 0.f;
    for (int i = blockIdx.x*blockDim.x + threadIdx.x; i < CC*CC*9; i += gridDim.x*blockDim.x)
        m = fmaxf(m, fabsf(w[i]));
    #pragma unroll
    for (int o = 16; o; o >>= 1) m = fmaxf(m, __shfl_xor_sync(~0u, m, o));
    __shared__ float sm[8];
    if ((threadIdx.x & 31) == 0) sm[threadIdx.x>>5] = m;
    __syncthreads();
    if (threadIdx.x < 32) {
        m = (threadIdx.x < (blockDim.x>>5)) ? sm[threadIdx.x] : 0.f;
        #pragma unroll
        for (int o = 16; o; o >>= 1) m = fmaxf(m, __shfl_xor_sync(~0u, m, o));
        if (threadIdx.x == 0) atomicMax(&g_alphaBits[blockIdx.y], __float_as_uint(m));
    }
}
// weights -> s8 quantized, [tap][oc][ci]
__global__ void k_wq8(const float* __restrict__ w1, const float* __restrict__ w2) {
    int conv = blockIdx.y;
    const float* w = conv ? w2 : w1;
    float alpha = __uint_as_float(g_alphaBits[conv]);
    int idx = blockIdx.x*blockDim.x + threadIdx.x;
    if (idx >= 9*128*128) return;
    int tap = idx >> 14, rem = idx & 16383, oc = rem >> 7, ci = rem & 127;
    float wc = fminf(fmaxf(w[((size_t)oc*CC + ci)*9 + tap] / alpha, -1.f), 1.f);
    g_wp8[conv][idx] = (signed char)__float2int_rn(wc * 7.f);
}
// x (NCHW f32) -> act_quant k (0..15) NHWC-padded
__global__ void k_quantA(const float* __restrict__ x) {
    __shared__ unsigned char s[128*64];
    int n = blockIdx.y, hw0 = blockIdx.x*64, tid = threadIdx.x;
    for (int i = tid; i < 8192; i += 256) {
        int c = i >> 6, px = i & 63;
        float v = x[((size_t)(n*CC + c))*HW + hw0 + px];
        s[c*64 + px] = (unsigned char)__float2int_rn(fminf(fmaxf(v, 0.f), 1.f) * 15.f);
    }
    __syncthreads();
    unsigned* A = (unsigned*)(g_act8 + (size_t)GUARD*128);
    for (int i = tid; i < 2048; i += 256) {
        int px = i >> 5, wd = i & 31, hw = hw0 + px;
        size_t p = (size_t)n*PPI + (hw/HH + 1)*PW + (hw%HH) + 1;
        int c0 = wd*4;
        unsigned word = (unsigned)s[c0*64+px] | ((unsigned)s[(c0+1)*64+px]<<8)
                      | ((unsigned)s[(c0+2)*64+px]<<16) | ((unsigned)s[(c0+3)*64+px]<<24);
        A[p*32 + wd] = word;
    }
}
// BN(S)+act_quant -> k (0..15) NHWC-padded
__global__ void k_bnq() {
    int idx = blockIdx.x*512 + threadIdx.x;
    int v = idx >> 5, q = idx & 31;
    int n = v / HW, hw = v % HW;
    size_t p = (size_t)n*PPI + (hw/HH + 1)*PW + (hw%HH) + 1;
    float4 sv = ((const float4*)(g_y + p*128))[q];
    int c0 = q*4;
    float f[4] = {sv.x, sv.y, sv.z, sv.w};
    unsigned word = 0;
    #pragma unroll
    for (int j = 0; j < 4; j++) {
        float bn = fmaf(g_coef[0][0][c0+j], f[j], g_coef[0][1][c0+j]);
        int k = __float2int_rn(fminf(fmaxf(bn, 0.f), 1.f) * 15.f);
        word |= (unsigned)k << (8*j);
    }
    *(unsigned*)(g_act8 + (size_t)GUARD*128 + p*128 + c0) = word;
}
__global__ void k_reduce(int slot) {
    __shared__ double sm[2][4][128];
    int c = threadIdx.x & 127, g = threadIdx.x >> 7;
    double s = 0.0, s2 = 0.0;
    int base = blockIdx.x*512;
    for (int j = 0; j < 128; j++) {
        int v = base + j*4 + g;
        int n = v / HW, hw = v % HW;
        size_t p = (size_t)n*PPI + (hw/HH + 1)*PW + (hw%HH) + 1;
        double val = (double)g_y[p*128 + c];
        s += val; s2 += val*val;
    }
    sm[0][g][c] = s; sm[1][g][c] = s2;
    __syncthreads();
    if (threadIdx.x < 128) {
        s  = sm[0][0][c]+sm[0][1][c]+sm[0][2][c]+sm[0][3][c];
        s2 = sm[1][0][c]+sm[1][1][c]+sm[1][2][c]+sm[1][3][c];
        atomicAdd(&g_red[slot][0][c], s);
        atomicAdd(&g_red[slot][1][c], s2);
    }
}
__global__ void k_stats(int slot, const float* __restrict__ gamma, const float* __restrict__ beta) {
    int c = threadIdx.x;
    double scale = (double)__uint_as_float(g_alphaBits[slot]) / 105.0;
    double mean = g_red[slot][0][c] / (double)NPX;
    double var  = g_red[slot][1][c] / (double)NPX - mean*mean;
    double rstd = 1.0 / sqrt(var*scale*scale + 1e-5);
    double g = (double)gamma[c];
    g_coef[slot][0][c] = (float)(g * rstd * scale);
    g_coef[slot][1][c] = (float)((double)beta[c] - g * rstd * mean * scale);
}
__global__ void k_final(const float* __restrict__ x, float* __restrict__ out) {
    __shared__ float sf[128*57];
    int y = blockIdx.x + 1, n = blockIdx.y, tid = threadIdx.x;
    size_t p0 = (size_t)n*PPI + y*PW + 1;
    for (int i = tid; i < 56*128; i += 256) {
        int px = i >> 7, c = i & 127;
        sf[c*57 + px] = g_y[(p0 + px)*128 + c];
    }
    __syncthreads();
    for (int i = tid; i < 128*56; i += 256) {
        int c = i / 56, px = i % 56;
        size_t o = ((size_t)(n*CC + c))*HW + (y-1)*HH + px;
        out[o] = fmaf(g_coef[1][0][c], sf[c*57+px], g_coef[1][1][c]) + x[o];
    }
}

// ---------------- IMMA conv: persistent, M=128 px x N=128 oc tiles ----------------
// smem: A double buffer 2 x 246 rows x 144B (pad for conflict-free LDS), then
//       B resident 9 taps x 128 oc x 128B with per-row 16B-chunk rotation.
#define AROWS 246
#define ASTR  144
#define SM_A0 0
#define SM_A1 (AROWS*ASTR)             // 35424
#define SM_B  (2*AROWS*ASTR)           // 70848
#define SM_SZ (SM_B + 9*128*128)       // 218304

__global__ void __launch_bounds__(256, 1) k_conv(int conv) {
    extern __shared__ __align__(128) char smem[];
    uint32_t sb = smem_u32(smem);
    int tid = threadIdx.x, wid = tid >> 5, lane = tid & 31;
    int g = lane >> 2, t = lane & 3;
    int mwarp = wid >> 2, nwarp = wid & 3;      // 2 x 4
    int pxw = mwarp * 64, ocb = nwarp * 32;

    const signed char* ABASE = g_act8 + (size_t)GUARD*128;
    unsigned long long Ag = (unsigned long long)__cvta_generic_to_global(ABASE);
    unsigned long long Bg = (unsigned long long)__cvta_generic_to_global(g_wp8[conv]);

    // stage B once (rotated chunks: phys chunk = (c + oc) & 7)
    for (int i = tid; i < 9216; i += 256) {
        int tap = i >> 10, r = i & 1023, oc = r >> 3, c = r & 7;
        cp16(sb + SM_B + tap*16384 + oc*128 + (((c + oc) & 7) << 4), Bg + (size_t)i*16);
    }
    // stage A for first tile
    long long tile = blockIdx.x;
    {
        unsigned long long src = Ag + (tile*128 - 59) * 128;
        for (int i = tid; i < 1968; i += 256)
            cp16(sb + SM_A0 + (i>>3)*ASTR + ((i&7)<<4), src + (size_t)i*16);
    }
    CP_COMMIT();

    int it = 0;
    for (; tile < NTIL; tile += gridDim.x, it++) {
        long long nxt = tile + gridDim.x;
        uint32_t curA = sb + ((it & 1) ? SM_A1 : SM_A0);
        if (nxt < NTIL) {
            uint32_t dst = sb + ((it & 1) ? SM_A0 : SM_A1);
            unsigned long long src = Ag + (nxt*128 - 59) * 128;
            for (int i = tid; i < 1968; i += 256)
                cp16(dst + (i>>3)*ASTR + ((i&7)<<4), src + (size_t)i*16);
            CP_COMMIT();
            CP_WAIT(1);
        } else {
            CP_WAIT(0);
        }
        __syncthreads();

        const char* bufc = smem + ((it & 1) ? SM_A1 : SM_A0);
        int acc[4][4][4];
        #pragma unroll
        for (int mt = 0; mt < 4; mt++)
            #pragma unroll
            for (int nt = 0; nt < 4; nt++)
                #pragma unroll
                for (int j = 0; j < 4; j++) acc[mt][nt][j] = 0;

        #pragma unroll 1
        for (int tap = 0; tap < 9; tap++) {
            int abase = pxw + c_off[tap] + 59 + g;
            const char* Bt = smem + SM_B + tap*16384;
            #pragma unroll
            for (int ks = 0; ks < 4; ks++) {
                int k0 = ks * 32;
                unsigned a[4][4];
                #pragma unroll
                for (int mt = 0; mt < 4; mt++) {
                    const char* ar = bufc + (abase + mt*16) * ASTR + k0 + 4*t;
                    a[mt][0] = *(const unsigned*)(ar);
                    a[mt][1] = *(const unsigned*)(ar + 8*ASTR);
                    a[mt][2] = *(const unsigned*)(ar + 16);
                    a[mt][3] = *(const unsigned*)(ar + 8*ASTR + 16);
                }
                #pragma unroll
                for (int nt = 0; nt < 4; nt++) {
                    int oc = ocb + nt*8 + g;
                    int ch0 = ((k0 >> 4) + oc) & 7;
                    int ch1 = ((k0 >> 4) + 1 + oc) & 7;
                    unsigned b0 = *(const unsigned*)(Bt + oc*128 + (ch0<<4) + 4*t);
                    unsigned b1 = *(const unsigned*)(Bt + oc*128 + (ch1<<4) + 4*t);
                    #pragma unroll
                    for (int mt = 0; mt < 4; mt++)
                        mma_s8(acc[mt][nt], a[mt][0], a[mt][1], a[mt][2], a[mt][3], b0, b1);
                }
            }
        }

        // epilogue: s32 -> f32, NHWC
        #pragma unroll
        for (int mt = 0; mt < 4; mt++) {
            size_t px0 = (size_t)tile*128 + pxw + mt*16 + g;
            #pragma unroll
            for (int nt = 0; nt < 4; nt++) {
                int oc = ocb + nt*8 + 2*t;
                float2 v0 = make_float2((float)acc[mt][nt][0], (float)acc[mt][nt][1]);
                float2 v1 = make_float2((float)acc[mt][nt][2], (float)acc[mt][nt][3]);
                *(float2*)(g_y + px0*128 + oc)       = v0;
                *(float2*)(g_y + (px0 + 8)*128 + oc) = v1;
            }
        }
        __syncthreads();   // protect buffer reuse before next stage overwrite
    }
}

// ---------------- launcher ----------------
extern "C" void kernel_launch(void* const* d_in, const int* in_sizes, int n_in,
                              void* d_out, int out_size) {
    const float* x      = (const float*)d_in[0];
    const float* w1     = (const float*)d_in[1];
    const float* w2     = (const float*)d_in[2];
    const float* gamma1 = (const float*)d_in[3];
    const float* beta1  = (const float*)d_in[4];
    const float* gamma2 = (const float*)d_in[5];
    const float* beta2  = (const float*)d_in[6];
    float* out = (float*)d_out;

    static int inited = 0;
    if (!inited) {
        cudaFuncSetAttribute(k_conv, cudaFuncAttributeMaxDynamicSharedMemorySize, SM_SZ);
        inited = 1;
    }

    k_zero<<<2, 256>>>();
    k_alpha<<<dim3(32, 2), 256>>>(w1, w2);
    k_wq8<<<dim3(576, 2), 256>>>(w1, w2);
    k_quantA<<<dim3(49, NB), 256>>>(x);

    k_conv<<<148, 256, SM_SZ>>>(0);
    k_reduce<<<392, 512>>>(0);
    k_stats<<<1, CC>>>(0, gamma1, beta1);

    k_bnq<<<NPX*32/512, 512>>>();
    k_conv<<<148, 256, SM_SZ>>>(1);
    k_reduce<<<392, 512>>>(1);
    k_stats<<<1, CC>>>(1, gamma2, beta2);

    k_final<<<dim3(HH, NB), 256>>>(x, out);
}

// round 5
// speedup vs baseline: 1.1145x; 1.1145x over previous
#include <cuda_runtime.h>
#include <cstdint>

#define CC   128
#define HH   56
#define NB   64
#define HW   3136
#define PW   58
#define PPI  (PW*PW)             // 3364
#define PTOT (NB*PPI)            // 215296
#define NTIL (PTOT/128)          // 1682
#define GUARD 64
#define NPX  (NB*HW)             // 200704

// ---------------- device scratch (zero-init at load; halo/guards never written) ----
__device__ unsigned g_alphaBits[2];
__device__ double   g_red[2][2][CC];
__device__ float    g_coef[2][2][CC];
__device__ __align__(128) signed char g_act8[(size_t)(PTOT + 2*GUARD) * CC]; // NHWC padded, k in 0..15
__device__ __align__(128) signed char g_wp8[2][9 * 128 * 128];               // [tap][oc][ci], m in -7..7
__device__ float    g_y[(size_t)PTOT * CC];                                   // S, NHWC f32 (exact ints)

// ---------------- helpers ----------------
__device__ __forceinline__ uint32_t smem_u32(const void* p) {
    uint32_t a; asm("{ .reg .u64 t; cvta.to.shared.u64 t, %1; cvt.u32.u64 %0, t; }":"=r"(a):"l"(p));
    return a;
}
__device__ __forceinline__ void cp16(uint32_t dst, unsigned long long src) {
    asm volatile("cp.async.cg.shared.global [%0], [%1], 16;"::"r"(dst),"l"(src));
}
#define CP_COMMIT() asm volatile("cp.async.commit_group;":::"memory")
#define CP_WAIT(n)  asm volatile("cp.async.wait_group %0;"::"n"(n):"memory")

__device__ __forceinline__ void mma_s8(int* c, unsigned a0, unsigned a1, unsigned a2, unsigned a3,
                                       unsigned b0, unsigned b1) {
    asm volatile("mma.sync.aligned.m16n8k32.row.col.s32.s8.s8.s32 "
                 "{%0,%1,%2,%3}, {%4,%5,%6,%7}, {%8,%9}, {%0,%1,%2,%3};"
                 : "+r"(c[0]), "+r"(c[1]), "+r"(c[2]), "+r"(c[3])
                 : "r"(a0), "r"(a1), "r"(a2), "r"(a3), "r"(b0), "r"(b1));
}
#define LDSM4(r0,r1,r2,r3,addr) \
    asm volatile("ldmatrix.sync.aligned.m8n8.x4.shared.b16 {%0,%1,%2,%3}, [%4];" \
                 : "=r"(r0),"=r"(r1),"=r"(r2),"=r"(r3) : "r"(addr))

// ---------------- small kernels ----------------
__global__ void k_zero() {
    int t = blockIdx.x*blockDim.x + threadIdx.x;
    if (t < 2) g_alphaBits[t] = 0u;
    if (t < 512) ((double*)g_red)[t] = 0.0;
}
__global__ void k_alpha(const float* __restrict__ w1, const float* __restrict__ w2) {
    const float* w = blockIdx.y ? w2 : w1;
    float m = 0.f;
    for (int i = blockIdx.x*blockDim.x + threadIdx.x; i < CC*CC*9; i += gridDim.x*blockDim.x)
        m = fmaxf(m, fabsf(w[i]));
    #pragma unroll
    for (int o = 16; o; o >>= 1) m = fmaxf(m, __shfl_xor_sync(~0u, m, o));
    __shared__ float sm[8];
    if ((threadIdx.x & 31) == 0) sm[threadIdx.x>>5] = m;
    __syncthreads();
    if (threadIdx.x < 32) {
        m = (threadIdx.x < (blockDim.x>>5)) ? sm[threadIdx.x] : 0.f;
        #pragma unroll
        for (int o = 16; o; o >>= 1) m = fmaxf(m, __shfl_xor_sync(~0u, m, o));
        if (threadIdx.x == 0) atomicMax(&g_alphaBits[blockIdx.y], __float_as_uint(m));
    }
}
// weights -> s8 quantized, [tap][oc][ci]
__global__ void k_wq8(const float* __restrict__ w1, const float* __restrict__ w2) {
    int conv = blockIdx.y;
    const float* w = conv ? w2 : w1;
    float alpha = __uint_as_float(g_alphaBits[conv]);
    int idx = blockIdx.x*blockDim.x + threadIdx.x;
    if (idx >= 9*128*128) return;
    int tap = idx >> 14, rem = idx & 16383, oc = rem >> 7, ci = rem & 127;
    float wc = fminf(fmaxf(w[((size_t)oc*CC + ci)*9 + tap] / alpha, -1.f), 1.f);
    g_wp8[conv][idx] = (signed char)__float2int_rn(wc * 7.f);
}
// x (NCHW f32) -> act_quant k (0..15) NHWC-padded; conflict-free word transpose
__global__ void k_quantA(const float* __restrict__ x) {
    __shared__ unsigned ws[32*65];
    int n = blockIdx.y, hw0 = blockIdx.x*64, tid = threadIdx.x;
    int c4 = tid >> 3, q = tid & 7;
    const float* xp = x + ((size_t)(n*CC + c4*4))*HW + hw0 + q*8;
    unsigned w[8] = {0,0,0,0,0,0,0,0};
    #pragma unroll
    for (int j = 0; j < 4; j++)
        #pragma unroll
        for (int p = 0; p < 8; p++) {
            float v = xp[(size_t)j*HW + p];
            int k = __float2int_rn(fminf(fmaxf(v, 0.f), 1.f) * 15.f);
            w[p] |= (unsigned)k << (8*j);
        }
    #pragma unroll
    for (int p = 0; p < 8; p++) ws[c4*65 + q*8 + p] = w[p];
    __syncthreads();
    unsigned* A = (unsigned*)(g_act8 + (size_t)GUARD*128);
    int wd = tid & 31;
    #pragma unroll
    for (int pl = tid >> 5; pl < 64; pl += 8) {
        int hw = hw0 + pl;
        size_t p = (size_t)n*PPI + (hw/HH + 1)*PW + (hw%HH) + 1;
        A[p*32 + wd] = ws[wd*65 + pl];
    }
}
// BN(S)+act_quant -> k (0..15) NHWC-padded
__global__ void k_bnq() {
    int idx = blockIdx.x*512 + threadIdx.x;
    int v = idx >> 5, q = idx & 31;
    int n = v / HW, hw = v % HW;
    size_t p = (size_t)n*PPI + (hw/HH + 1)*PW + (hw%HH) + 1;
    float4 sv = ((const float4*)(g_y + p*128))[q];
    int c0 = q*4;
    float f[4] = {sv.x, sv.y, sv.z, sv.w};
    unsigned word = 0;
    #pragma unroll
    for (int j = 0; j < 4; j++) {
        float bn = fmaf(g_coef[0][0][c0+j], f[j], g_coef[0][1][c0+j]);
        int k = __float2int_rn(fminf(fmaxf(bn, 0.f), 1.f) * 15.f);
        word |= (unsigned)k << (8*j);
    }
    *(unsigned*)(g_act8 + (size_t)GUARD*128 + p*128 + c0) = word;
}
__global__ void k_reduce(int slot) {
    __shared__ double sm[2][4][128];
    int c = threadIdx.x & 127, g = threadIdx.x >> 7;
    double s = 0.0, s2 = 0.0;
    int base = blockIdx.x*512;
    for (int j = 0; j < 128; j++) {
        int v = base + j*4 + g;
        int n = v / HW, hw = v % HW;
        size_t p = (size_t)n*PPI + (hw/HH + 1)*PW + (hw%HH) + 1;
        double val = (double)g_y[p*128 + c];
        s += val; s2 += val*val;
    }
    sm[0][g][c] = s; sm[1][g][c] = s2;
    __syncthreads();
    if (threadIdx.x < 128) {
        s  = sm[0][0][c]+sm[0][1][c]+sm[0][2][c]+sm[0][3][c];
        s2 = sm[1][0][c]+sm[1][1][c]+sm[1][2][c]+sm[1][3][c];
        atomicAdd(&g_red[slot][0][c], s);
        atomicAdd(&g_red[slot][1][c], s2);
    }
}
__global__ void k_stats(int slot, const float* __restrict__ gamma, const float* __restrict__ beta) {
    int c = threadIdx.x;
    double scale = (double)__uint_as_float(g_alphaBits[slot]) / 105.0;
    double mean = g_red[slot][0][c] / (double)NPX;
    double var  = g_red[slot][1][c] / (double)NPX - mean*mean;
    double rstd = 1.0 / sqrt(var*scale*scale + 1e-5);
    double g = (double)gamma[c];
    g_coef[slot][0][c] = (float)(g * rstd * scale);
    g_coef[slot][1][c] = (float)((double)beta[c] - g * rstd * mean * scale);
}
__global__ void k_final(const float* __restrict__ x, float* __restrict__ out) {
    __shared__ float sf[128*57];
    int y = blockIdx.x + 1, n = blockIdx.y, tid = threadIdx.x;
    size_t p0 = (size_t)n*PPI + y*PW + 1;
    for (int i = tid; i < 56*128; i += 256) {
        int px = i >> 7, c = i & 127;
        sf[c*57 + px] = g_y[(p0 + px)*128 + c];
    }
    __syncthreads();
    for (int i = tid; i < 128*56; i += 256) {
        int c = i / 56, px = i % 56;
        size_t o = ((size_t)(n*CC + c))*HW + (y-1)*HH + px;
        out[o] = fmaf(g_coef[1][0][c], sf[c*57+px], g_coef[1][1][c]) + x[o];
    }
}

// ---------------- IMMA conv: 512 thr, 16 warps (32px x 32oc each), ldmatrix ----
#define AROWS 246
#define ASTR  144
#define SM_A0 0
#define SM_A1 (AROWS*ASTR)             // 35424
#define SM_B  (2*AROWS*ASTR)           // 70848
#define SM_SZ (SM_B + 9*128*128)       // 218304

__global__ void __launch_bounds__(512, 1) k_conv(int conv) {
    extern __shared__ __align__(128) char smem[];
    uint32_t sb = smem_u32(smem);
    int tid = threadIdx.x, wid = tid >> 5, lane = tid & 31;
    int mwarp = wid >> 2, nwarp = wid & 3;      // 4 x 4 warps
    int pxw = mwarp * 32, ocb = nwarp * 32;

    const signed char* ABASE = g_act8 + (size_t)GUARD*128;
    unsigned long long Ag = (unsigned long long)__cvta_generic_to_global(ABASE);
    unsigned long long Bg = (unsigned long long)__cvta_generic_to_global(g_wp8[conv]);

    // ldmatrix lane geometry
    int lm = lane >> 3, lr = lane & 7;
    uint32_t a_lane = (uint32_t)(((lm & 1)*8 + lr) * ASTR + (lm >> 1)*16);
    int b_oc  = ocb + (lm >> 1)*8 + lr;         // oc for pair base (pair1 = +16)
    int b_cad = lm & 1;                         // chunk +0/+1
    uint32_t b_base = sb + SM_B + (uint32_t)b_oc*128;

    // stage B once (rotated chunks: phys chunk = (c + oc) & 7)
    for (int i = tid; i < 9216; i += 512) {
        int tap = i >> 10, r = i & 1023, oc = r >> 3, c = r & 7;
        cp16(sb + SM_B + tap*16384 + oc*128 + (((c + oc) & 7) << 4), Bg + (size_t)i*16);
    }
    // stage A for first tile
    long long tile = blockIdx.x;
    {
        unsigned long long src = Ag + (tile*128 - 59) * 128;
        for (int i = tid; i < 1968; i += 512)
            cp16(sb + SM_A0 + (i>>3)*ASTR + ((i&7)<<4), src + (size_t)i*16);
    }
    CP_COMMIT();

    const int offs[9] = {-59,-58,-57,-1,0,1,57,58,59};
    int it = 0;
    for (; tile < NTIL; tile += gridDim.x, it++) {
        long long nxt = tile + gridDim.x;
        if (nxt < NTIL) {
            uint32_t dst = sb + ((it & 1) ? SM_A0 : SM_A1);
            unsigned long long src = Ag + (nxt*128 - 59) * 128;
            for (int i = tid; i < 1968; i += 512)
                cp16(dst + (i>>3)*ASTR + ((i&7)<<4), src + (size_t)i*16);
            CP_COMMIT();
            CP_WAIT(1);
        } else {
            CP_WAIT(0);
        }
        __syncthreads();

        uint32_t curA = sb + ((it & 1) ? SM_A1 : SM_A0);
        int acc[2][4][4];
        #pragma unroll
        for (int mt = 0; mt < 2; mt++)
            #pragma unroll
            for (int nt = 0; nt < 4; nt++)
                #pragma unroll
                for (int j = 0; j < 4; j++) acc[mt][nt][j] = 0;

        #pragma unroll
        for (int tap = 0; tap < 9; tap++) {
            uint32_t aTap = curA + (uint32_t)(pxw + offs[tap] + 59) * ASTR + a_lane;
            uint32_t bTap = b_base + (uint32_t)tap * 16384;
            #pragma unroll
            for (int ks = 0; ks < 4; ks++) {
                uint32_t rot = (uint32_t)(((2*ks + b_cad + b_oc) & 7) << 4);
                unsigned a0[4], a1[4], b[8];
                LDSM4(a0[0], a0[1], a0[2], a0[3], aTap + ks*32);
                LDSM4(a1[0], a1[1], a1[2], a1[3], aTap + ks*32 + 16*ASTR);
                LDSM4(b[0], b[1], b[2], b[3], bTap + rot);           // nt 0,1
                LDSM4(b[4], b[5], b[6], b[7], bTap + rot + 2048);    // nt 2,3
                #pragma unroll
                for (int nt = 0; nt < 4; nt++) {
                    mma_s8(acc[0][nt], a0[0], a0[1], a0[2], a0[3], b[nt*2], b[nt*2+1]);
                    mma_s8(acc[1][nt], a1[0], a1[1], a1[2], a1[3], b[nt*2], b[nt*2+1]);
                }
            }
        }

        // epilogue: s32 -> f32, NHWC
        int g = lane >> 2, t = lane & 3;
        #pragma unroll
        for (int mt = 0; mt < 2; mt++) {
            size_t px0 = (size_t)tile*128 + pxw + mt*16 + g;
            #pragma unroll
            for (int nt = 0; nt < 4; nt++) {
                int oc = ocb + nt*8 + 2*t;
                *(float2*)(g_y + px0*128 + oc) =
                    make_float2((float)acc[mt][nt][0], (float)acc[mt][nt][1]);
                *(float2*)(g_y + (px0 + 8)*128 + oc) =
                    make_float2((float)acc[mt][nt][2], (float)acc[mt][nt][3]);
            }
        }
        __syncthreads();   // protect buffer reuse before next stage overwrite
    }
}

// ---------------- launcher ----------------
extern "C" void kernel_launch(void* const* d_in, const int* in_sizes, int n_in,
                              void* d_out, int out_size) {
    const float* x      = (const float*)d_in[0];
    const float* w1     = (const float*)d_in[1];
    const float* w2     = (const float*)d_in[2];
    const float* gamma1 = (const float*)d_in[3];
    const float* beta1  = (const float*)d_in[4];
    const float* gamma2 = (const float*)d_in[5];
    const float* beta2  = (const float*)d_in[6];
    float* out = (float*)d_out;

    static int inited = 0;
    if (!inited) {
        cudaFuncSetAttribute(k_conv, cudaFuncAttributeMaxDynamicSharedMemorySize, SM_SZ);
        inited = 1;
    }

    k_zero<<<2, 256>>>();
    k_alpha<<<dim3(32, 2), 256>>>(w1, w2);
    k_wq8<<<dim3(576, 2), 256>>>(w1, w2);
    k_quantA<<<dim3(49, NB), 256>>>(x);

    k_conv<<<152, 512, SM_SZ>>>(0);
    k_reduce<<<392, 512>>>(0);
    k_stats<<<1, CC>>>(0, gamma1, beta1);

    k_bnq<<<NPX*32/512, 512>>>();
    k_conv<<<152, 512, SM_SZ>>>(1);
    k_reduce<<<392, 512>>>(1);
    k_stats<<<1, CC>>>(1, gamma2, beta2);

    k_final<<<dim3(HH, NB), 256>>>(x, out);
}